// round 4
// baseline (speedup 1.0000x reference)
#include <cuda_runtime.h>

#define B_  4
#define N_  8192
#define C_  64
#define M_  2048
#define NW_ 7
#define NSLOT 14            // 7 windows x 2 key-chunks
#define QB_ROWS 256
#define KSTEP 64
#define KST 68
#define VST 72
#define SSTAGE (64*KST + 64*VST)   // 8960 words per stage
#define SCALE_LOG2 0.18033688011112042f  // (1/8) * log2(e)

__device__ float g_Q[B_*N_*C_];
__device__ float g_K[B_*N_*C_];
__device__ float g_V[B_*N_*C_];
__device__ float g_O[(long)B_*NSLOT*M_*C_];   // ~29.4 MB
__device__ float g_D[B_*NSLOT*M_];

// job table: {qb, chunk, ks0, ks1}, sorted heaviest-first (LPT)
__constant__ int4 c_jobs[12] = {
    {7,0,0,16},{7,1,16,32},{3,0,0,16},
    {6,0,0,14},{6,1,14,28},
    {5,0,0,12},{5,1,12,24},{2,0,0,12},
    {4,0,0,10},{4,1,10,20},
    {1,0,0,8},{0,0,0,4}
};

__device__ __forceinline__ unsigned tf32u(float x) {
    unsigned u; asm("cvt.rna.tf32.f32 %0, %1;" : "=r"(u) : "f"(x)); return u;
}
__device__ __forceinline__ float ex2(float x) {
    float y; asm("ex2.approx.f32 %0, %1;" : "=f"(y) : "f"(x)); return y;
}
__device__ __forceinline__ void mma8(float d[4], const unsigned a[4], unsigned b0, unsigned b1) {
    asm volatile("mma.sync.aligned.m16n8k8.row.col.f32.tf32.tf32.f32 "
        "{%0,%1,%2,%3},{%4,%5,%6,%7},{%8,%9},{%0,%1,%2,%3};"
        : "+f"(d[0]), "+f"(d[1]), "+f"(d[2]), "+f"(d[3])
        : "r"(a[0]), "r"(a[1]), "r"(a[2]), "r"(a[3]), "r"(b0), "r"(b1));
}

// ============================ Kernel 1: QKV (scalar fp32) ============================
__global__ __launch_bounds__(256) void qkv_kernel(const float* __restrict__ x,
                                                  const float* __restrict__ Wq,
                                                  const float* __restrict__ Wk,
                                                  const float* __restrict__ Wv) {
    extern __shared__ float sm1[];
    float* xT = sm1;
    float* Ws = sm1 + 4096;
    const int tid = threadIdx.x;
    const long rowbase = (long)blockIdx.x * 64;

    #pragma unroll
    for (int k = 0; k < 4; k++) {
        int l = tid + k*256;
        int row = l & 63, cg = l >> 6;
        float4 v = *(const float4*)(x + (rowbase + row)*C_ + cg*4);
        xT[(cg*4+0)*64 + row] = v.x;
        xT[(cg*4+1)*64 + row] = v.y;
        xT[(cg*4+2)*64 + row] = v.z;
        xT[(cg*4+3)*64 + row] = v.w;
    }
    {
        const float* Wm[3] = {Wq, Wk, Wv};
        #pragma unroll
        for (int m = 0; m < 3; m++)
            #pragma unroll
            for (int k = 0; k < 4; k++) {
                int l = tid + k*256;
                int cc = l >> 4, jg = l & 15;
                *(float4*)&Ws[cc*192 + m*64 + jg*4] = *(const float4*)(Wm[m] + cc*64 + jg*4);
            }
    }
    __syncthreads();

    const int ty = tid >> 4, tx = tid & 15;
    float acc[3][4][4];
    #pragma unroll
    for (int m = 0; m < 3; m++)
        #pragma unroll
        for (int i = 0; i < 4; i++)
            #pragma unroll
            for (int j = 0; j < 4; j++) acc[m][i][j] = 0.f;

    const float* xp = xT + ty*4;
    #pragma unroll 4
    for (int cc = 0; cc < 64; cc++) {
        float4 xv = *(const float4*)(xp + cc*64);
        float4 w0 = *(const float4*)(Ws + cc*192 +   0 + tx*4);
        float4 w1 = *(const float4*)(Ws + cc*192 +  64 + tx*4);
        float4 w2 = *(const float4*)(Ws + cc*192 + 128 + tx*4);
        float xs[4] = {xv.x, xv.y, xv.z, xv.w};
        float wq[4] = {w0.x, w0.y, w0.z, w0.w};
        float wk[4] = {w1.x, w1.y, w1.z, w1.w};
        float wv[4] = {w2.x, w2.y, w2.z, w2.w};
        #pragma unroll
        for (int i = 0; i < 4; i++)
            #pragma unroll
            for (int j = 0; j < 4; j++) {
                acc[0][i][j] += xs[i]*wq[j];
                acc[1][i][j] += xs[i]*wk[j];
                acc[2][i][j] += xs[i]*wv[j];
            }
    }
    #pragma unroll
    for (int i = 0; i < 4; i++) {
        long rr = (rowbase + ty*4 + i)*C_ + tx*4;
        *(float4*)&g_Q[rr] = make_float4(acc[0][i][0]*SCALE_LOG2, acc[0][i][1]*SCALE_LOG2,
                                         acc[0][i][2]*SCALE_LOG2, acc[0][i][3]*SCALE_LOG2);
        *(float4*)&g_K[rr] = make_float4(acc[1][i][0], acc[1][i][1], acc[1][i][2], acc[1][i][3]);
        *(float4*)&g_V[rr] = make_float4(acc[2][i][0], acc[2][i][1], acc[2][i][2], acc[2][i][3]);
    }
}

// ==================== Kernel 2: tf32 flash attention, cp.async pipelined ====================
#define PREFETCH(KS, STAGE) do {                                                            \
    _Pragma("unroll")                                                                       \
    for (int i_ = 0; i_ < 4; i_++) {                                                        \
        int l_ = tid + i_*256;                                                              \
        int slot_ = l_ >> 4, cg_ = (l_ & 15) << 2;                                          \
        int srck_ = (slot_ & ~7) | ((slot_ & 1) << 2) | ((slot_ & 7) >> 1);                 \
        unsigned dk_ = smbase + (((STAGE)*SSTAGE + slot_*KST + cg_) << 2);                  \
        unsigned dv_ = smbase + (((STAGE)*SSTAGE + 64*KST + slot_*VST + cg_) << 2);         \
        asm volatile("cp.async.cg.shared.global [%0], [%1], 16;"                            \
            :: "r"(dk_), "l"(Kg + (long)((KS)*KSTEP + srck_)*rs + cg_));                    \
        asm volatile("cp.async.cg.shared.global [%0], [%1], 16;"                            \
            :: "r"(dv_), "l"(Vg + (long)((KS)*KSTEP + slot_)*rs + cg_));                    \
    }                                                                                       \
    asm volatile("cp.async.commit_group;");                                                 \
} while (0)

__global__ __launch_bounds__(256, 1) void attn_kernel() {
    extern __shared__ float smf[];
    const int tid  = threadIdx.x;
    const int wid  = tid >> 5, lane = tid & 31;
    const int g    = lane >> 2, t4 = lane & 3;
    const int blk  = blockIdx.x;
    const int4 jb  = c_jobs[blk / 28];
    const int w    = blk % 28;
    const int b    = w / NW_, wi = w % NW_;
    const int qb   = jb.x, chunk = jb.y, ks0 = jb.z, ks1 = jb.w;

    int base, r;
    if      (wi < 4) { base = wi*2048;     r = 1; }
    else if (wi < 6) { base = (wi-4)*4096; r = 2; }
    else             { base = 0;           r = 4; }

    const float* Qg = g_Q + ((long)b*N_ + base)*C_;
    const float* Kg = g_K + ((long)b*N_ + base)*C_;
    const float* Vg = g_V + ((long)b*N_ + base)*C_;
    const int rs = r * C_;
    const unsigned smbase = (unsigned)__cvta_generic_to_shared(smf);

    // ---- Q fragments in registers for whole kernel (cvt.rna) ----
    const int row0 = qb*QB_ROWS + 32*wid;
    unsigned qa[2][8][4];
    #pragma unroll
    for (int mt = 0; mt < 2; mt++) {
        const float* q0 = Qg + (long)(row0 + 16*mt + g)*rs;
        const float* q1 = q0 + (long)8*rs;
        #pragma unroll
        for (int s = 0; s < 8; s++) {
            qa[mt][s][0] = tf32u(q0[8*s + t4]);
            qa[mt][s][1] = tf32u(q1[8*s + t4]);
            qa[mt][s][2] = tf32u(q0[8*s + t4 + 4]);
            qa[mt][s][3] = tf32u(q1[8*s + t4 + 4]);
        }
    }

    float oacc[2][8][4];
    float mrow[2][2], lrow[2][2];
    #pragma unroll
    for (int mt = 0; mt < 2; mt++) {
        mrow[mt][0] = mrow[mt][1] = -1e30f;
        lrow[mt][0] = lrow[mt][1] = 0.f;
        #pragma unroll
        for (int j = 0; j < 8; j++)
            #pragma unroll
            for (int q = 0; q < 4; q++) oacc[mt][j][q] = 0.f;
    }

    PREFETCH(ks0, 0);
    asm volatile("cp.async.wait_group 0;");
    __syncthreads();

    for (int ks = ks0; ks < ks1; ks++) {
        const int cur = (ks - ks0) & 1;
        if (ks + 1 < ks1) PREFETCH(ks + 1, cur ^ 1);

        const unsigned* Ks = (const unsigned*)smf + (size_t)cur * SSTAGE;
        const unsigned* Vs = Ks + 64*KST;

        // ---- S = Q K^T ----
        float sacc[2][8][4];
        #pragma unroll
        for (int mt = 0; mt < 2; mt++)
            #pragma unroll
            for (int j = 0; j < 8; j++)
                #pragma unroll
                for (int q = 0; q < 4; q++) sacc[mt][j][q] = 0.f;

        #pragma unroll
        for (int s = 0; s < 8; s++) {
            #pragma unroll
            for (int j = 0; j < 8; j++) {
                unsigned b0 = Ks[(8*j + g)*KST + 8*s + t4];
                unsigned b1 = Ks[(8*j + g)*KST + 8*s + t4 + 4];
                mma8(sacc[0][j], qa[0][s], b0, b1);
                mma8(sacc[1][j], qa[1][s], b0, b1);
            }
        }

        // ---- causal mask (diagonal 64-blocks only) ----
        if (ks >= 4*qb) {
            #pragma unroll
            for (int mt = 0; mt < 2; mt++) {
                int r0_ = row0 + 16*mt + g, r1_ = r0_ + 8;
                #pragma unroll
                for (int j = 0; j < 8; j++) {
                    int k0 = ks*KSTEP + 8*j + t4, k1 = k0 + 4;
                    if (k0 > r0_) sacc[mt][j][0] = -1e30f;
                    if (k1 > r0_) sacc[mt][j][1] = -1e30f;
                    if (k0 > r1_) sacc[mt][j][2] = -1e30f;
                    if (k1 > r1_) sacc[mt][j][3] = -1e30f;
                }
            }
        }

        // ---- online softmax (log2 domain) ----
        #pragma unroll
        for (int mt = 0; mt < 2; mt++) {
            float rm0 = -1e30f, rm1 = -1e30f;
            #pragma unroll
            for (int j = 0; j < 8; j++) {
                rm0 = fmaxf(rm0, fmaxf(sacc[mt][j][0], sacc[mt][j][1]));
                rm1 = fmaxf(rm1, fmaxf(sacc[mt][j][2], sacc[mt][j][3]));
            }
            rm0 = fmaxf(rm0, __shfl_xor_sync(0xffffffffu, rm0, 1));
            rm0 = fmaxf(rm0, __shfl_xor_sync(0xffffffffu, rm0, 2));
            rm1 = fmaxf(rm1, __shfl_xor_sync(0xffffffffu, rm1, 1));
            rm1 = fmaxf(rm1, __shfl_xor_sync(0xffffffffu, rm1, 2));
            float mn0 = fmaxf(mrow[mt][0], rm0), mn1 = fmaxf(mrow[mt][1], rm1);
            float c0 = ex2(mrow[mt][0] - mn0),   c1 = ex2(mrow[mt][1] - mn1);
            mrow[mt][0] = mn0; mrow[mt][1] = mn1;
            float rs0 = 0.f, rs1 = 0.f;
            #pragma unroll
            for (int j = 0; j < 8; j++) {
                float p0 = ex2(sacc[mt][j][0] - mn0); rs0 += p0; sacc[mt][j][0] = p0;
                float p1 = ex2(sacc[mt][j][1] - mn0); rs0 += p1; sacc[mt][j][1] = p1;
                float p2 = ex2(sacc[mt][j][2] - mn1); rs1 += p2; sacc[mt][j][2] = p2;
                float p3 = ex2(sacc[mt][j][3] - mn1); rs1 += p3; sacc[mt][j][3] = p3;
            }
            rs0 += __shfl_xor_sync(0xffffffffu, rs0, 1);
            rs0 += __shfl_xor_sync(0xffffffffu, rs0, 2);
            rs1 += __shfl_xor_sync(0xffffffffu, rs1, 1);
            rs1 += __shfl_xor_sync(0xffffffffu, rs1, 2);
            lrow[mt][0] = lrow[mt][0]*c0 + rs0;
            lrow[mt][1] = lrow[mt][1]*c1 + rs1;
            #pragma unroll
            for (int jv = 0; jv < 8; jv++) {
                oacc[mt][jv][0] *= c0; oacc[mt][jv][1] *= c0;
                oacc[mt][jv][2] *= c1; oacc[mt][jv][3] *= c1;
            }
        }

        // ---- O += P V (S C-frags -> A-frags via kappa permutation) ----
        #pragma unroll
        for (int s2 = 0; s2 < 8; s2++) {
            unsigned pa0[4] = { tf32u(sacc[0][s2][0]), tf32u(sacc[0][s2][2]),
                                tf32u(sacc[0][s2][1]), tf32u(sacc[0][s2][3]) };
            unsigned pa1[4] = { tf32u(sacc[1][s2][0]), tf32u(sacc[1][s2][2]),
                                tf32u(sacc[1][s2][1]), tf32u(sacc[1][s2][3]) };
            #pragma unroll
            for (int jv = 0; jv < 8; jv++) {
                unsigned b0 = Vs[(8*s2 + t4)*VST + 8*jv + g];
                unsigned b1 = Vs[(8*s2 + t4 + 4)*VST + 8*jv + g];
                mma8(oacc[0][jv], pa0, b0, b1);
                mma8(oacc[1][jv], pa1, b0, b1);
            }
        }

        if (ks + 1 < ks1) asm volatile("cp.async.wait_group 0;");
        __syncthreads();
    }

    // ---- epilogue: normalized O + denominator d = l * 2^m, per slot ----
    const long slot = (long)b*NSLOT + wi + 7*chunk;
    float* Og = g_O + slot*M_*C_;
    float* Dg = g_D + slot*M_;
    #pragma unroll
    for (int mt = 0; mt < 2; mt++) {
        int r0_ = row0 + 16*mt + g, r1_ = r0_ + 8;
        float i0 = 1.0f / lrow[mt][0], i1 = 1.0f / lrow[mt][1];
        #pragma unroll
        for (int jv = 0; jv < 8; jv++) {
            *(float2*)&Og[(long)r0_*C_ + 8*jv + 2*t4] =
                make_float2(oacc[mt][jv][0]*i0, oacc[mt][jv][1]*i0);
            *(float2*)&Og[(long)r1_*C_ + 8*jv + 2*t4] =
                make_float2(oacc[mt][jv][2]*i1, oacc[mt][jv][3]*i1);
        }
        if (t4 == 0) {
            Dg[r0_] = lrow[mt][0] * ex2(mrow[mt][0]);
            Dg[r1_] = lrow[mt][1] * ex2(mrow[mt][1]);
        }
    }
}

// ============================ Kernel 3: mix (LSE merge across slots) ============================
__global__ __launch_bounds__(256) void mix_kernel(float* __restrict__ out) {
    const int tid = threadIdx.x;
    const int c = tid & 63;
    const int gp = blockIdx.x*4 + (tid >> 6);
    const int b = gp >> 13;
    const int p = gp & (N_-1);

    float dsum = 0.f, num = 0.f;
    #define ACC1(SLOT, ROW) do {                               \
        long i_ = ((long)b*NSLOT + (SLOT))*M_ + (ROW);         \
        float d_ = g_D[i_];                                    \
        dsum += d_;                                            \
        num  += d_ * g_O[i_*C_ + c];                           \
    } while (0)

    int w0 = p >> 11, r0 = p & 2047;
    ACC1(w0, r0);
    if ((r0 >> 8) >= 4) ACC1(w0 + 7, r0);
    if ((p & 1) == 0) {
        int w1 = 4 + (p >> 12), r1 = (p & 4095) >> 1;
        ACC1(w1, r1);
        if ((r1 >> 8) >= 4) ACC1(w1 + 7, r1);
    }
    if ((p & 3) == 0) {
        int r2 = p >> 2;
        ACC1(6, r2);
        if ((r2 >> 8) >= 4) ACC1(13, r2);
    }
    out[((long)b*N_ + p)*C_ + c] = num / dsum;
    #undef ACC1
}

// =======================================================================
extern "C" void kernel_launch(void* const* d_in, const int* in_sizes, int n_in,
                              void* d_out, int out_size) {
    (void)in_sizes; (void)n_in; (void)out_size;
    const float* x  = (const float*)d_in[0];
    const float* Wq = (const float*)d_in[1];
    const float* Wk = (const float*)d_in[2];
    const float* Wv = (const float*)d_in[3];
    float* out = (float*)d_out;

    const int smem1 = (64*64 + 64*192) * 4;
    const int smem2 = 2 * SSTAGE * 4;   // 71680 B
    cudaFuncSetAttribute(qkv_kernel,  cudaFuncAttributeMaxDynamicSharedMemorySize, smem1);
    cudaFuncSetAttribute(attn_kernel, cudaFuncAttributeMaxDynamicSharedMemorySize, smem2);

    qkv_kernel<<<(B_*N_)/64, 256, smem1>>>(x, Wq, Wk, Wv);
    attn_kernel<<<12*28, 256, smem2>>>();
    mix_kernel<<<(B_*N_)/4, 256>>>(out);
}